// round 15
// baseline (speedup 1.0000x reference)
#include <cuda_runtime.h>
#include <stdint.h>

#define T_DIM 8
#define C_DIM 4
#define H_DIM 1024
#define W_DIM 1024
#define NIMG  (T_DIM * C_DIM)
#define NGRID 16
#define NCELLS (NGRID * NGRID)
#define THRESH 0.65f
#define NUM_FG 40
#define NUM_BG 1
#define MAX_PTS 42
#define ROW_F4 (W_DIM / 4)     // 256 float4 per image row
#define BLOCKS_PER_IMG 32      // block = (cell-row, half): 64 rows x 512 cols
#define NSTAGE 5               // smem ring depth (5 x 8KB = 40KB, static)
#define NSTEPS 16              // 64 rows / 4 rows per stage
#define STAGE_BYTES 8192       // 4 rows x 512 cols x 4B

// Scratch (__device__ globals). Each cell has exactly ONE writer warp ->
// plain stores are idempotent across graph replays (no init kernel).
__device__ unsigned long long g_cmax[NIMG * NCELLS]; // (score_bits<<32) | ~flat_idx
__device__ unsigned long long g_cmin[NIMG * NCELLS]; // (score_bits<<32) |  flat_idx
__device__ unsigned int       g_cnt[NIMG];           // arrival counters; last block resets to 0

static __device__ __forceinline__ unsigned long long umaxll(unsigned long long a, unsigned long long b){ return a > b ? a : b; }
static __device__ __forceinline__ unsigned long long uminll(unsigned long long a, unsigned long long b){ return a < b ? a : b; }

static __device__ __forceinline__ unsigned smem_u32(const void* p) {
    return (unsigned)__cvta_generic_to_shared(p);
}

#define MBAR_INIT(addr, cnt) \
    asm volatile("mbarrier.init.shared.b64 [%0], %1;" :: "r"(addr), "r"(cnt) : "memory")
#define MBAR_EXPECT_TX(addr, bytes) \
    asm volatile("mbarrier.arrive.expect_tx.shared.b64 _, [%0], %1;" :: "r"(addr), "r"(bytes) : "memory")
#define BULK_G2S(dst, src, bytes, bar) \
    asm volatile("cp.async.bulk.shared::cluster.global.mbarrier::complete_tx::bytes [%0], [%1], %2, [%3];" \
                 :: "r"(dst), "l"(src), "r"(bytes), "r"(bar) : "memory")

static __device__ __forceinline__ void mbar_wait_parity(unsigned addr, unsigned parity) {
    unsigned done;
    asm volatile(
        "{\n\t.reg .pred p;\n\t"
        "mbarrier.try_wait.parity.acquire.cta.shared::cta.b64 p, [%1], %2;\n\t"
        "selp.b32 %0, 1, 0, p;\n\t}"
        : "=r"(done) : "r"(addr), "r"(parity) : "memory");
    if (!done) {
        asm volatile(
            "{\n\t.reg .pred P1;\n\t"
            "WAIT_LOOP_%=:\n\t"
            "mbarrier.try_wait.parity.acquire.cta.shared::cta.b64 P1, [%0], %1, 0x989680;\n\t"
            "@P1 bra.uni WAIT_DONE_%=;\n\t"
            "bra.uni WAIT_LOOP_%=;\n\t"
            "WAIT_DONE_%=:\n\t}"
            :: "r"(addr), "r"(parity) : "memory");
    }
}

__global__ void __launch_bounds__(256)
fused_kernel(const float* __restrict__ sim,
             const int*   __restrict__ ori,
             float*       __restrict__ out,
             int write_nums)
{
    const int blk  = blockIdx.x;             // 0..1023
    const int img  = blk >> 5;               // 32 images
    const int sub  = blk & 31;
    const int cy   = sub >> 1;               // cell row 0..15
    const int half = sub & 1;                // column half: cols [half*512, half*512+512)
    const int tid  = threadIdx.x;
    const int w    = tid >> 5;               // warp 0..7: owns cell cx = half*8 + w
    const int lane = tid & 31;
    const float* gbase = sim + (size_t)img * (H_DIM * W_DIM);

    __shared__ __align__(16) float s_stage[NSTAGE][STAGE_BYTES / 4]; // 5 x 8KB
    __shared__ unsigned long long s_bar[NSTAGE];

    const unsigned bar0 = smem_u32(&s_bar[0]);
    const unsigned stg0 = smem_u32(&s_stage[0][0]);

    if (tid == 0) {
        #pragma unroll
        for (int s = 0; s < NSTAGE; s++) MBAR_INIT(bar0 + s * 8, 1);
    }
    __syncthreads();

    // issue stage s: 4 image rows (cy*64 + s*4 + r), cols [half*512, +512) -> 4 x 2KB copies
    #define ISSUE(s) do {                                                             \
        const int b_ = (s) % NSTAGE;                                                  \
        MBAR_EXPECT_TX(bar0 + b_ * 8, STAGE_BYTES);                                   \
        const float* src_ = gbase + (size_t)(cy * 64 + (s) * 4) * W_DIM + half * 512; \
        unsigned dst_ = stg0 + b_ * STAGE_BYTES;                                      \
        _Pragma("unroll")                                                             \
        for (int r_ = 0; r_ < 4; r_++)                                                \
            BULK_G2S(dst_ + r_ * 2048, src_ + r_ * W_DIM, 2048, bar0 + b_ * 8);       \
    } while (0)

    if (tid == 0) {
        #pragma unroll
        for (int s = 0; s < NSTAGE; s++) ISSUE(s);
    }

    // Lane geometry: per stage (4 rows x 512 cols), warp w's cell slice is
    // 4 rows x 64 cols. Lane covers rows r0 and r0+2, float4 col4 of the cell.
    const int r0   = lane >> 4;              // 0..1
    const int col4 = lane & 15;              // 0..15

    const float INF = __uint_as_float(0x7f800000u);
    float vmax = 0.0f, vmin = INF;           // scores in [0,1): safe bounds, bit-monotone
    int bsmax = 0, bsmin = 0;

    #pragma unroll
    for (int s = 0; s < NSTEPS; s++) {
        const int b = s % NSTAGE;
        mbar_wait_parity(bar0 + b * 8, (unsigned)((s / NSTAGE) & 1));

        const float4* sp = (const float4*)&s_stage[b][0];   // 4 rows x 128 f4/row
        float4 a0 = sp[ r0      * 128 + w * 16 + col4];
        float4 a1 = sp[(r0 + 2) * 128 + w * 16 + col4];

        float mx = fmaxf(fmaxf(fmaxf(a0.x, a0.y), fmaxf(a0.z, a0.w)),
                         fmaxf(fmaxf(a1.x, a1.y), fmaxf(a1.z, a1.w)));
        float mn = fminf(fminf(fminf(a0.x, a0.y), fminf(a0.z, a0.w)),
                         fminf(fminf(a1.x, a1.y), fminf(a1.z, a1.w)));
        // Strict compare keeps the FIRST stage achieving the extremum
        // (stages ascend in flat index).
        if (mx > vmax) { vmax = mx; bsmax = s; }
        if (mn < vmin) { vmin = mn; bsmin = s; }

        __syncthreads();                     // all warps done with buffer b
        if (tid == 0 && s + NSTAGE < NSTEPS) ISSUE(s + NSTAGE);
    }

    // Warp value reductions (scores positive -> unsigned bit order == float order).
    float wmax = __uint_as_float(__reduce_max_sync(0xffffffffu, __float_as_uint(vmax)));
    float wmin = __uint_as_float(__reduce_min_sync(0xffffffffu, __float_as_uint(vmin)));

    // Deferred index resolution: matching lanes re-load their 2 float4 of the
    // best stage from GLOBAL (L2) and scan DESCENDING flat order so overwrite
    // keeps the smallest flat index (reference first-occurrence semantics).
    const float4* gf4 = (const float4*)gbase;
    unsigned candMax = 0xffffffffu, candMin = 0xffffffffu;
    if (vmax == wmax) {
        const int s = bsmax;
        const int rA = cy * 64 + s * 4 + r0;         // lane's first row (smaller idx)
        const int cb = half * 128 + w * 16 + col4;   // float4 column in image
        float4 v1 = __ldcg(gf4 + (size_t)(rA + 2) * ROW_F4 + cb);
        float4 v0 = __ldcg(gf4 + (size_t)rA * ROW_F4 + cb);
        unsigned i1 = (unsigned)((rA + 2) * W_DIM + cb * 4);
        unsigned i0 = (unsigned)(rA * W_DIM + cb * 4);
        if (v1.w == wmax) candMax = i1 + 3;
        if (v1.z == wmax) candMax = i1 + 2;
        if (v1.y == wmax) candMax = i1 + 1;
        if (v1.x == wmax) candMax = i1;
        if (v0.w == wmax) candMax = i0 + 3;
        if (v0.z == wmax) candMax = i0 + 2;
        if (v0.y == wmax) candMax = i0 + 1;
        if (v0.x == wmax) candMax = i0;
    }
    if (vmin == wmin) {
        const int s = bsmin;
        const int rA = cy * 64 + s * 4 + r0;
        const int cb = half * 128 + w * 16 + col4;
        float4 v1 = __ldcg(gf4 + (size_t)(rA + 2) * ROW_F4 + cb);
        float4 v0 = __ldcg(gf4 + (size_t)rA * ROW_F4 + cb);
        unsigned i1 = (unsigned)((rA + 2) * W_DIM + cb * 4);
        unsigned i0 = (unsigned)(rA * W_DIM + cb * 4);
        if (v1.w == wmin) candMin = i1 + 3;
        if (v1.z == wmin) candMin = i1 + 2;
        if (v1.y == wmin) candMin = i1 + 1;
        if (v1.x == wmin) candMin = i1;
        if (v0.w == wmin) candMin = i0 + 3;
        if (v0.z == wmin) candMin = i0 + 2;
        if (v0.y == wmin) candMin = i0 + 1;
        if (v0.x == wmin) candMin = i0;
    }
    candMax = __reduce_min_sync(0xffffffffu, candMax);
    candMin = __reduce_min_sync(0xffffffffu, candMin);

    if (lane == 0) {
        const int cell = cy * 16 + half * 8 + w;
        g_cmax[img * NCELLS + cell] =
            ((unsigned long long)__float_as_uint(wmax) << 32) | (unsigned)(~candMax);
        g_cmin[img * NCELLS + cell] =
            ((unsigned long long)__float_as_uint(wmin) << 32) | candMin;
        __threadfence();                     // release: only storing lanes pay the fence
    }

    // ---------------- handoff: last of 32 blocks per image finalizes ----------------
    __syncthreads();
    __shared__ int sLast;
    if (tid == 0) {
        unsigned prev = atomicAdd(&g_cnt[img], 1u);
        int last = (prev == BLOCKS_PER_IMG - 1);
        if (last) g_cnt[img] = 0;            // self-reset for next graph replay
        sLast = last;
    }
    __syncthreads();
    if (!sLast) return;
    __threadfence();                         // acquire side

    // ---------------- Phase 2: finalize (one block per image) ----------------
    const int t = img / C_DIM;
    const float sx = (float)ori[t * 2 + 1] / (float)W_DIM;
    const float sy = (float)ori[t * 2 + 0] / (float)H_DIM;

    __shared__ unsigned long long key[NCELLS];
    __shared__ unsigned long long sG[16];    // [0:8) img-max partials, [8:16) img-min partials

    unsigned long long pM = __ldcg(&g_cmax[img * NCELLS + tid]);
    unsigned long long pN = __ldcg(&g_cmin[img * NCELLS + tid]);
    unsigned bits = (unsigned)(pM >> 32);
    unsigned pidx = ~(unsigned)(pM & 0xffffffffull);
    bool valid = __uint_as_float(bits) > THRESH;    // fg cell iff its max exceeds threshold

    // Unique sort key: descending score, ascending cell id; invalid cells last (stable by cid).
    unsigned long long k = valid ? ((pM & 0xFFFFFFFF00000000ULL) | (unsigned)(255 - tid))
                                 : (unsigned long long)(unsigned)(255 - tid);
    key[tid] = k;

    // Image-global extrema.
    unsigned long long gm = pM, gn = pN;
    #pragma unroll
    for (int off = 16; off; off >>= 1) {
        gm = umaxll(gm, __shfl_xor_sync(0xffffffffu, gm, off));
        gn = uminll(gn, __shfl_xor_sync(0xffffffffu, gn, off));
    }
    if (lane == 0) { sG[w] = gm; sG[8 + w] = gn; }

    int nvalid = __syncthreads_count((int)valid);

    int rank = 0;
    #pragma unroll 8
    for (int j = 0; j < NCELLS; j++) rank += (key[j] > k) ? 1 : 0;

    bool any_fg  = (nvalid > 0);
    int fg_count = any_fg ? (nvalid < NUM_FG ? nvalid : NUM_FG) : 1;

    float* o = out + (size_t)img * MAX_PTS * 4;
    if (tid < MAX_PTS * 4) o[tid] = 0.0f;    // 168 < 256: full zero of this image's block
    __syncthreads();

    if (any_fg) {
        if (rank < NUM_FG && valid) {
            float s  = __uint_as_float(bits);
            float px = (float)(pidx % W_DIM);
            float py = (float)(pidx / W_DIM);
            float* r = o + rank * 4;
            r[0] = px * sx; r[1] = py * sy; r[2] = s; r[3] = 1.0f;
        }
    } else if (tid == 0) {
        unsigned long long m = sG[0];
        #pragma unroll
        for (int i = 1; i < 8; i++) m = umaxll(m, sG[i]);
        unsigned gb = (unsigned)(m >> 32);
        unsigned gi = ~(unsigned)(m & 0xffffffffull);
        o[0] = (float)(gi % W_DIM) * sx;
        o[1] = (float)(gi / W_DIM) * sy;
        o[2] = __uint_as_float(gb);
        o[3] = 1.0f;
    }

    if (tid == 0) {
        unsigned long long n = sG[8];
        #pragma unroll
        for (int i = 1; i < 8; i++) n = uminll(n, sG[8 + i]);
        unsigned bb = (unsigned)(n >> 32);
        unsigned bi = (unsigned)(n & 0xffffffffull);
        float* r = o + fg_count * 4;
        r[0] = (float)(bi % W_DIM) * sx;
        r[1] = (float)(bi / W_DIM) * sy;
        r[2] = __uint_as_float(bb);
        r[3] = 0.0f;
        if (write_nums) {
            float* nums = out + (size_t)NIMG * MAX_PTS * 4;
            nums[img] = (float)(fg_count + NUM_BG);
        }
    }
}

extern "C" void kernel_launch(void* const* d_in, const int* in_sizes, int n_in,
                              void* d_out, int out_size) {
    const float* sim = (const float*)d_in[0];
    // d_in[1] = category_ids (unused by the reference output)
    const int* ori = (const int*)d_in[2];

    int write_nums = (out_size >= NIMG * MAX_PTS * 4 + NIMG) ? 1 : 0;
    fused_kernel<<<NIMG * BLOCKS_PER_IMG, 256>>>(sim, ori, (float*)d_out, write_nums);
}